// round 16
// baseline (speedup 1.0000x reference)
#include <cuda_runtime.h>
#include <cuda_fp16.h>

#define Q_  32
#define LQ_ 32
#define D_  256
#define LD_ 192
#define H_  768
#define DT_ 128
#define DC_ 768

// Scratch (allocation-free: __device__ globals)
__device__ float g_doc_reps[(size_t)D_ * LD_ * DT_];   // 25.2 MB
__device__ float g_qry_reps[(size_t)Q_ * LQ_ * DT_];
__device__ float g_doc_cls[(size_t)D_ * DC_];
__device__ float g_qry_cls[(size_t)Q_ * DC_];
__device__ float g_scores[(size_t)Q_ * D_];

// Mega-GEMM block ranges (128x128 output tiles)
#define NB_DOCREP 384
#define NB_QRYREP 8
#define NB_DOCCLS 12
#define NB_QRYCLS 6
#define NB_TOTAL  (NB_DOCREP + NB_QRYREP + NB_DOCCLS + NB_QRYCLS)

#define AS_STRIDE 8       // uints (half2) per A row; frag LDS.64 conflict-free
#define BS_STRIDE 136     // uints per B k-pair row; 136%32==8 -> conflict-free

__device__ __forceinline__ unsigned pack_h2(float lo, float hi) {
    __half2 h = __floats2half2_rn(lo, hi);   // .x = lo half (lower k index)
    return *reinterpret_cast<unsigned*>(&h);
}

// ---------------------------------------------------------------------------
// fp16 tensor-core mega-GEMM (mma.m16n8k16.row.col.f32.f16.f16.f32),
// double-buffered, 2 CTAs/SM (__launch_bounds__ minBlocks=2 doubles resident
// warps -> doubles outstanding DRAM loads; R14 showed 24% HBM / 20% occ).
// BM=BN=128, BK=16, 256 thr = 8 warps (2x4), warp tile 64x32.
// ---------------------------------------------------------------------------
__global__ __launch_bounds__(256, 2) void mega_gemm_tc(
    const float* __restrict__ doc_hidden,
    const float* __restrict__ qry_hidden,
    const float* __restrict__ tok_w, const float* __restrict__ tok_b,
    const float* __restrict__ cls_w, const float* __restrict__ cls_b,
    float* __restrict__ doc_reps, float* __restrict__ qry_reps,
    float* __restrict__ doc_cls,  float* __restrict__ qry_cls)
{
    const int BK = 16;
    const int NIT = H_ / BK;                     // 48 (even)
    __shared__ unsigned As[2][128 * AS_STRIDE];  // [buf][m*8 + slot]
    __shared__ unsigned Bs[2][8 * BS_STRIDE];    // [buf][k2*136 + n]

    // --- segment dispatch ---
    const float* A; const float* B; const float* bias; float* C;
    int lda, ldb, ldc, M, bm, bn, relu;
    int blk = blockIdx.x;
    if (blk < NB_DOCREP) {
        A = doc_hidden; lda = H_;        B = tok_w; ldb = DT_; bias = tok_b;
        C = doc_reps;   ldc = DT_;       M = D_ * LD_;
        bm = blk * 128; bn = 0;          relu = 1;
    } else if (blk < NB_DOCREP + NB_QRYREP) {
        int t = blk - NB_DOCREP;
        A = qry_hidden; lda = H_;        B = tok_w; ldb = DT_; bias = tok_b;
        C = qry_reps;   ldc = DT_;       M = Q_ * LQ_;
        bm = t * 128;   bn = 0;          relu = 1;
    } else if (blk < NB_DOCREP + NB_QRYREP + NB_DOCCLS) {
        int t = blk - NB_DOCREP - NB_QRYREP;
        A = doc_hidden; lda = LD_ * H_;  B = cls_w; ldb = DC_; bias = cls_b;
        C = doc_cls;    ldc = DC_;       M = D_;
        bm = (t % 2) * 128; bn = (t / 2) * 128; relu = 0;
    } else {
        int t = blk - NB_DOCREP - NB_QRYREP - NB_DOCCLS;
        A = qry_hidden; lda = LQ_ * H_;  B = cls_w; ldb = DC_; bias = cls_b;
        C = qry_cls;    ldc = DC_;       M = Q_;
        bm = 0;         bn = t * 128;    relu = 0;
    }

    int tid  = threadIdx.x;
    int lane = tid & 31;
    int wid  = tid >> 5;
    int warp_m = (wid >> 2) * 64;
    int warp_n = (wid & 3) * 32;
    int grp = lane >> 2;
    int tig = lane & 3;

    float c[4][4][4];
#pragma unroll
    for (int mt = 0; mt < 4; mt++)
#pragma unroll
        for (int nt = 0; nt < 4; nt++)
#pragma unroll
            for (int r = 0; r < 4; r++) c[mt][nt][r] = 0.f;

    // A staging: thread -> (row, sel). Loads float4 at k = sel*4 and sel*4+8;
    // packs 4 half2 slots. Fragment read: uint2 = ((k2t,k2t+1),(k2t+8,k2t+9)).
    int a_row = tid >> 1;
    int a_sel = tid & 1;
    bool a_ok = (bm + a_row < M);
    const float* a_src = A + (size_t)(bm + a_row) * lda + a_sel * 4;

    // B staging: thread -> (k2 = tid>>5, n_base = (tid&31)*4); half2(k-even,k-odd).
    int b_k2 = tid >> 5;
    int b_nb = (tid & 31) * 4;
    const float* b_src0 = B + (size_t)(2 * b_k2)     * ldb + bn + b_nb;
    const float* b_src1 = B + (size_t)(2 * b_k2 + 1) * ldb + bn + b_nb;

    float va0[4], va1[4], vb0[4], vb1[4];

#define LOAD_SLAB(k0) do {                                                    \
        if (a_ok) {                                                           \
            float4 t0 = *reinterpret_cast<const float4*>(a_src + (k0));       \
            float4 t1 = *reinterpret_cast<const float4*>(a_src + (k0) + 8);   \
            va0[0]=t0.x; va0[1]=t0.y; va0[2]=t0.z; va0[3]=t0.w;               \
            va1[0]=t1.x; va1[1]=t1.y; va1[2]=t1.z; va1[3]=t1.w;               \
        } else {                                                              \
            va0[0]=va0[1]=va0[2]=va0[3]=0.f;                                  \
            va1[0]=va1[1]=va1[2]=va1[3]=0.f;                                  \
        }                                                                     \
        float4 u0 = *reinterpret_cast<const float4*>(b_src0 + (size_t)(k0) * ldb); \
        float4 u1 = *reinterpret_cast<const float4*>(b_src1 + (size_t)(k0) * ldb); \
        vb0[0]=u0.x; vb0[1]=u0.y; vb0[2]=u0.z; vb0[3]=u0.w;                   \
        vb1[0]=u1.x; vb1[1]=u1.y; vb1[2]=u1.z; vb1[3]=u1.w;                   \
    } while (0)

#define STAGE(buf) do {                                                      \
        *reinterpret_cast<uint4*>(&As[buf][a_row * AS_STRIDE + a_sel * 4]) =  \
            make_uint4(pack_h2(va0[0], va0[1]), pack_h2(va1[0], va1[1]),      \
                       pack_h2(va0[2], va0[3]), pack_h2(va1[2], va1[3]));     \
        *reinterpret_cast<uint4*>(&Bs[buf][b_k2 * BS_STRIDE + b_nb]) =        \
            make_uint4(pack_h2(vb0[0], vb1[0]), pack_h2(vb0[1], vb1[1]),      \
                       pack_h2(vb0[2], vb1[2]), pack_h2(vb0[3], vb1[3]));     \
    } while (0)

#define MMA_BUF(cur) do {                                                     \
        unsigned bf[4][2];                                                    \
        _Pragma("unroll")                                                     \
        for (int nt = 0; nt < 4; nt++) {                                      \
            int n = warp_n + nt * 8 + grp;                                    \
            bf[nt][0] = Bs[cur][tig * BS_STRIDE + n];                         \
            bf[nt][1] = Bs[cur][(tig + 4) * BS_STRIDE + n];                   \
        }                                                                     \
        _Pragma("unroll")                                                     \
        for (int mt = 0; mt < 4; mt++) {                                      \
            int m = warp_m + mt * 16 + grp;                                   \
            uint2 plo = *reinterpret_cast<const uint2*>(&As[cur][m * AS_STRIDE + tig * 2]);       \
            uint2 phi = *reinterpret_cast<const uint2*>(&As[cur][(m + 8) * AS_STRIDE + tig * 2]); \
            _Pragma("unroll")                                                 \
            for (int nt = 0; nt < 4; nt++) {                                  \
                asm volatile(                                                 \
                    "mma.sync.aligned.m16n8k16.row.col.f32.f16.f16.f32 "     \
                    "{%0,%1,%2,%3}, {%4,%5,%6,%7}, {%8,%9}, {%0,%1,%2,%3};\n" \
                    : "+f"(c[mt][nt][0]), "+f"(c[mt][nt][1]),                 \
                      "+f"(c[mt][nt][2]), "+f"(c[mt][nt][3])                  \
                    : "r"(plo.x), "r"(phi.x), "r"(plo.y), "r"(phi.y),         \
                      "r"(bf[nt][0]), "r"(bf[nt][1]));                        \
            }                                                                 \
        }                                                                     \
    } while (0)

    // --- prologue ---
    LOAD_SLAB(0);
    STAGE(0);
    __syncthreads();

    // unroll-by-2 over slabs: buffer index is compile-time constant
    for (int it = 0; it < NIT; it += 2) {
        // slab it (buf 0)
        LOAD_SLAB((it + 1) * BK);
        MMA_BUF(0);
        STAGE(1);
        __syncthreads();
        // slab it+1 (buf 1)
        if (it + 2 < NIT) LOAD_SLAB((it + 2) * BK);
        MMA_BUF(1);
        if (it + 2 < NIT) STAGE(0);
        __syncthreads();
    }
#undef LOAD_SLAB
#undef STAGE
#undef MMA_BUF

    // --- epilogue: bias (+relu), float2 stores ---
#pragma unroll
    for (int mt = 0; mt < 4; mt++) {
#pragma unroll
        for (int nt = 0; nt < 4; nt++) {
            int m0 = bm + warp_m + mt * 16 + grp;
            int n0 = bn + warp_n + nt * 8 + tig * 2;
            float b0 = bias[n0], b1 = bias[n0 + 1];
            if (m0 < M) {
                float v0 = c[mt][nt][0] + b0;
                float v1 = c[mt][nt][1] + b1;
                if (relu) { v0 = fmaxf(v0, 0.f); v1 = fmaxf(v1, 0.f); }
                *reinterpret_cast<float2*>(C + (size_t)m0 * ldc + n0) = make_float2(v0, v1);
            }
            if (m0 + 8 < M) {
                float v2 = c[mt][nt][2] + b0;
                float v3 = c[mt][nt][3] + b1;
                if (relu) { v2 = fmaxf(v2, 0.f); v3 = fmaxf(v3, 0.f); }
                *reinterpret_cast<float2*>(C + (size_t)(m0 + 8) * ldc + n0) = make_float2(v2, v3);
            }
        }
    }
}

// Disambiguate the two 1024-element inputs on device.
__device__ __forceinline__ bool is_mask_arr(const void* p) {
    const unsigned* u = (const unsigned*)p;
    return u[0] == 0x3F800000u && u[1] == 0x3F800000u && u[2] == 0x3F800000u;
}

// ---------------------------------------------------------------------------
// Sparse exact-match token scoring + fused cls dot. Block = (q, 8 docs).
// ---------------------------------------------------------------------------
__global__ __launch_bounds__(128) void tok_kernel(
    const void* __restrict__ cand_a, const void* __restrict__ cand_b,
    const int* __restrict__ dids_g,
    float* __restrict__ scores)
{
    bool a_mask = is_mask_arr(cand_a);
    const int*   qids_g  = (const int*)  (a_mask ? cand_b : cand_a);
    const float* qmask_g = (const float*)(a_mask ? cand_a : cand_b);

    __shared__ float qs[LQ_][DT_];
    __shared__ float qcls[DC_];
    __shared__ int   s_qids[LQ_];
    __shared__ float s_qmask[LQ_];
    __shared__ int   s_dids[LD_];
    __shared__ float warp_acc[4];
    __shared__ float warp_cls[4];

    int q   = blockIdx.x;
    int d0  = blockIdx.y * 8;
    int tid = threadIdx.x;
    int lane = tid & 31;
    int w    = tid >> 5;

    for (int t = tid; t < LQ_ * DT_; t += 128)
        qs[t / DT_][t % DT_] = g_qry_reps[(size_t)q * LQ_ * DT_ + t];
    for (int t = tid; t < DC_; t += 128)
        qcls[t] = g_qry_cls[(size_t)q * DC_ + t];
    if (tid < LQ_) {
        s_qids[tid]  = qids_g[q * LQ_ + tid];
        s_qmask[tid] = qmask_g[q * LQ_ + tid];
    }
    __syncthreads();

    for (int dd = 0; dd < 8; dd++) {
        int d = d0 + dd;
        for (int t = tid; t < LD_; t += 128)
            s_dids[t] = dids_g[d * LD_ + t];
        __syncthreads();

        const float* drep = g_doc_reps + (size_t)d * LD_ * DT_;
        float acc = 0.f;

        for (int i = 1 + w; i < LQ_; i += 4) {
            int tok = s_qids[i];
            float best = 0.f;
#pragma unroll
            for (int jb = 0; jb < LD_; jb += 32) {
                int j = jb + lane;
                unsigned mask = __ballot_sync(0xffffffffu, s_dids[j] == tok);
                while (mask) {
                    int jj = jb + (__ffs(mask) - 1);
                    mask &= mask - 1;
                    const float* dr = drep + (size_t)jj * DT_;
                    float p = qs[i][lane]      * dr[lane]
                            + qs[i][lane + 32] * dr[lane + 32]
                            + qs[i][lane + 64] * dr[lane + 64]
                            + qs[i][lane + 96] * dr[lane + 96];
#pragma unroll
                    for (int off = 16; off > 0; off >>= 1)
                        p += __shfl_xor_sync(0xffffffffu, p, off);
                    best = fmaxf(best, p);
                }
            }
            acc += best * s_qmask[i];
        }

        const float* dcls = g_doc_cls + (size_t)d * DC_;
        float pc = 0.f;
#pragma unroll
        for (int k = 0; k < DC_ / 128; k++)
            pc += qcls[k * 128 + tid] * dcls[k * 128 + tid];
#pragma unroll
        for (int off = 16; off > 0; off >>= 1)
            pc += __shfl_xor_sync(0xffffffffu, pc, off);

        if (lane == 0) { warp_acc[w] = acc; warp_cls[w] = pc; }
        __syncthreads();
        if (tid == 0)
            scores[q * D_ + d] = warp_acc[0] + warp_acc[1] + warp_acc[2] + warp_acc[3]
                               + warp_cls[0] + warp_cls[1] + warp_cls[2] + warp_cls[3];
        __syncthreads();
    }
}

// ---------------------------------------------------------------------------
// Fused loss + output layout.
// ---------------------------------------------------------------------------
__global__ __launch_bounds__(1024) void loss_layout_kernel(
    const float* __restrict__ scores, const int* __restrict__ gs,
    float* __restrict__ out, int out_size, int mode)
{
    __shared__ float wloss[32];
    __shared__ float s_loss;
    int tid = threadIdx.x;
    int lane = tid & 31;
    int w = tid >> 5;

    const float* row = scores + (size_t)w * D_;
    float m = -1e30f;
    for (int c = lane; c < D_; c += 32) m = fmaxf(m, row[c]);
#pragma unroll
    for (int off = 16; off > 0; off >>= 1)
        m = fmaxf(m, __shfl_xor_sync(0xffffffffu, m, off));
    float s = 0.f;
    for (int c = lane; c < D_; c += 32) s += expf(row[c] - m);
#pragma unroll
    for (int off = 16; off > 0; off >>= 1)
        s += __shfl_xor_sync(0xffffffffu, s, off);

    int group = 8;
    if (gs) {
        int gv = gs[0];
        if (gv >= 1 && gv * 31 < D_) group = gv;
    }
    int label = w * group;
    float logp = row[label] - m - logf(s);
    if (lane == 0) wloss[w] = -logp;
    __syncthreads();
    if (tid == 0) {
        float t = 0.f;
        for (int i = 0; i < 32; i++) t += wloss[i];
        s_loss = t / 32.f;
    }
    __syncthreads();

    float loss = s_loss;
    for (int i = tid; i < out_size; i += 1024) {
        if (mode == 0) {
            if (i == 0) out[0] = loss;
        } else if (mode == 1) {
            out[i] = (i < Q_ * D_) ? scores[i] : 0.f;
        } else {
            if (i == 0) out[0] = loss;
            else out[i] = (i - 1 < Q_ * D_) ? scores[i - 1] : 0.f;
        }
    }
}

// Diagnostic sentinel
__global__ void diag_kernel(float* out, int missing_mask, int n)
{
    int i = blockIdx.x * blockDim.x + threadIdx.x;
    if (i < n) out[i] = (i == 0) ? (-1.0e6f - (float)missing_mask) : 0.f;
}

// ---------------------------------------------------------------------------
extern "C" void kernel_launch(void* const* d_in, const int* in_sizes, int n_in,
                              void* d_out, int out_size)
{
    const float* qry_hidden = nullptr;
    const float* doc_hidden = nullptr;
    const void*  doc_ids    = nullptr;
    const float* tok_w      = nullptr;
    const float* tok_b      = nullptr;
    const float* cls_w      = nullptr;
    const float* cls_b      = nullptr;
    const int*   gsize      = nullptr;
    const void*  cand_a     = nullptr;
    const void*  cand_b     = nullptr;

    long long div = 0;
    for (int i = 0; i < n_in; i++) {
        if (in_sizes[i] == 37748736)  { div = 1; break; }
        if (in_sizes[i] == 150994944) { div = 4; break; }
    }
    if (div == 0) div = 1;

    for (int i = 0; i < n_in; i++) {
        long long sz = (long long)in_sizes[i] / div;
        switch (sz) {
            case 786432:   qry_hidden = (const float*)d_in[i]; break;
            case 37748736: doc_hidden = (const float*)d_in[i]; break;
            case 49152:    doc_ids    = d_in[i];               break;
            case 98304:    tok_w      = (const float*)d_in[i]; break;
            case 128:      tok_b      = (const float*)d_in[i]; break;
            case 589824:   cls_w      = (const float*)d_in[i]; break;
            case 768:      cls_b      = (const float*)d_in[i]; break;
            case 1:        gsize      = (const int*)d_in[i];   break;
            case 1024:
                if (!cand_a) cand_a = d_in[i]; else cand_b = d_in[i];
                break;
            default:
                if (sz == 2 && div == 4) gsize = (const int*)d_in[i];
                break;
        }
    }

    float* out = (float*)d_out;

    int missing = 0;
    if (!qry_hidden) missing |= 1;
    if (!doc_hidden) missing |= 2;
    if (!doc_ids)    missing |= 4;
    if (!tok_w)      missing |= 8;
    if (!tok_b)      missing |= 16;
    if (!cls_w)      missing |= 32;
    if (!cls_b)      missing |= 64;
    if (!cand_a)     missing |= 128;
    if (!cand_b)     missing |= 256;
    if (missing) {
        int n = out_size > 0 ? out_size : 1;
        diag_kernel<<<(n + 255) / 256, 256>>>(out, missing, n);
        return;
    }

    float *doc_reps, *qry_reps, *doc_cls, *qry_cls, *scores;
    cudaGetSymbolAddress((void**)&doc_reps, g_doc_reps);
    cudaGetSymbolAddress((void**)&qry_reps, g_qry_reps);
    cudaGetSymbolAddress((void**)&doc_cls,  g_doc_cls);
    cudaGetSymbolAddress((void**)&qry_cls,  g_qry_cls);
    cudaGetSymbolAddress((void**)&scores,   g_scores);

    mega_gemm_tc<<<NB_TOTAL, 256>>>(doc_hidden, qry_hidden,
                                    tok_w, tok_b, cls_w, cls_b,
                                    doc_reps, qry_reps, doc_cls, qry_cls);
    {
        dim3 grid(Q_, D_ / 8);
        tok_kernel<<<grid, 128>>>(cand_a, cand_b, (const int*)doc_ids, scores);
    }
    int mode = (out_size == 1) ? 0 : (out_size == Q_ * D_) ? 1 : 2;
    loss_layout_kernel<<<1, 1024>>>(scores, gsize, out, out_size, mode);
}

// round 17
// speedup vs baseline: 1.1585x; 1.1585x over previous
#include <cuda_runtime.h>
#include <cuda_fp16.h>

#define Q_  32
#define LQ_ 32
#define D_  256
#define LD_ 192
#define H_  768
#define DT_ 128
#define DC_ 768

// Scratch (allocation-free: __device__ globals)
__device__ float    g_doc_reps[(size_t)D_ * LD_ * DT_];   // 25.2 MB
__device__ float    g_qry_reps[(size_t)Q_ * LQ_ * DT_];
__device__ float    g_doc_cls[(size_t)D_ * DC_];
__device__ float    g_qry_cls[(size_t)Q_ * DC_];
__device__ float    g_scores[(size_t)Q_ * D_];
__device__ unsigned g_union[32];                          // query-token id bitmap

// Mega-GEMM block ranges (128x128 output tiles)
#define NB_DOCREP 384
#define NB_QRYREP 8
#define NB_DOCCLS 12
#define NB_QRYCLS 6
#define NB_TOTAL  (NB_DOCREP + NB_QRYREP + NB_DOCCLS + NB_QRYCLS)

#define AS_STRIDE 8       // uints (half2) per A row; frag LDS.64 conflict-free
#define BS_STRIDE 136     // uints per B k-pair row; conflict-free scalar frags

__device__ __forceinline__ unsigned pack_h2(float lo, float hi) {
    __half2 h = __floats2half2_rn(lo, hi);
    return *reinterpret_cast<unsigned*>(&h);
}

// Disambiguate the two 1024-element inputs on device.
__device__ __forceinline__ bool is_mask_arr(const void* p) {
    const unsigned* u = (const unsigned*)p;
    return u[0] == 0x3F800000u && u[1] == 0x3F800000u && u[2] == 0x3F800000u;
}

// union bitmap membership; out-of-range ids = matched (conservative)
__device__ __forceinline__ bool in_union_s(const unsigned* un, int id) {
    if ((unsigned)id >= 1024u) return true;
    return (un[id >> 5] >> (id & 31)) & 1u;
}

// ---------------------------------------------------------------------------
// Build bitmap of all query token ids at positions >= 1 (the only tokens the
// max-pool ever uses). One block, 1024 threads.
// ---------------------------------------------------------------------------
__global__ void prep_union(const void* __restrict__ ca, const void* __restrict__ cb)
{
    const int* qids = is_mask_arr(ca) ? (const int*)cb : (const int*)ca;
    int t = threadIdx.x;
    if (t < 32) g_union[t] = 0u;
    __syncthreads();
    if ((t & 31) != 0) {                       // exclude position 0 (CLS)
        int id = qids[t];
        if ((unsigned)id < 1024u)
            atomicOr(&g_union[id >> 5], 1u << (id & 31));
    }
}

// ---------------------------------------------------------------------------
// fp16 tensor-core mega-GEMM (R14 config: 256 thr, 1 CTA target, dynamic
// double-buffering) + union-bitmap row skipping in the docrep segment:
// doc-token rows whose id is not in any query skip the A load and C store.
// ---------------------------------------------------------------------------
__global__ __launch_bounds__(256) void mega_gemm_tc(
    const float* __restrict__ doc_hidden,
    const float* __restrict__ qry_hidden,
    const int*   __restrict__ doc_ids,
    const float* __restrict__ tok_w, const float* __restrict__ tok_b,
    const float* __restrict__ cls_w, const float* __restrict__ cls_b,
    float* __restrict__ doc_reps, float* __restrict__ qry_reps,
    float* __restrict__ doc_cls,  float* __restrict__ qry_cls)
{
    const int BK = 16;
    const int NIT = H_ / BK;                     // 48
    __shared__ unsigned As[2][128 * AS_STRIDE];
    __shared__ unsigned Bs[2][8 * BS_STRIDE];
    __shared__ unsigned s_un[32];

    const float* A; const float* B; const float* bias; float* C;
    int lda, ldb, ldc, M, bm, bn, relu;
    int blk = blockIdx.x;
    bool is_docrep = (blk < NB_DOCREP);
    if (blk < NB_DOCREP) {
        A = doc_hidden; lda = H_;        B = tok_w; ldb = DT_; bias = tok_b;
        C = doc_reps;   ldc = DT_;       M = D_ * LD_;
        bm = blk * 128; bn = 0;          relu = 1;
    } else if (blk < NB_DOCREP + NB_QRYREP) {
        int t = blk - NB_DOCREP;
        A = qry_hidden; lda = H_;        B = tok_w; ldb = DT_; bias = tok_b;
        C = qry_reps;   ldc = DT_;       M = Q_ * LQ_;
        bm = t * 128;   bn = 0;          relu = 1;
    } else if (blk < NB_DOCREP + NB_QRYREP + NB_DOCCLS) {
        int t = blk - NB_DOCREP - NB_QRYREP;
        A = doc_hidden; lda = LD_ * H_;  B = cls_w; ldb = DC_; bias = cls_b;
        C = doc_cls;    ldc = DC_;       M = D_;
        bm = (t % 2) * 128; bn = (t / 2) * 128; relu = 0;
    } else {
        int t = blk - NB_DOCREP - NB_QRYREP - NB_DOCCLS;
        A = qry_hidden; lda = LQ_ * H_;  B = cls_w; ldb = DC_; bias = cls_b;
        C = qry_cls;    ldc = DC_;       M = Q_;
        bm = 0;         bn = t * 128;    relu = 0;
    }

    int tid  = threadIdx.x;
    int lane = tid & 31;
    int wid  = tid >> 5;
    int warp_m = (wid >> 2) * 64;
    int warp_n = (wid & 3) * 32;
    int grp = lane >> 2;
    int tig = lane & 3;

    if (tid < 32) s_un[tid] = g_union[tid];
    __syncthreads();

    float c[4][4][4];
#pragma unroll
    for (int mt = 0; mt < 4; mt++)
#pragma unroll
        for (int nt = 0; nt < 4; nt++)
#pragma unroll
            for (int r = 0; r < 4; r++) c[mt][nt][r] = 0.f;

    int a_row = tid >> 1;
    int a_sel = tid & 1;
    bool a_ok = (bm + a_row < M);
    bool a_load = a_ok;
    if (is_docrep && a_ok)
        a_load = in_union_s(s_un, doc_ids[bm + a_row]);
    const float* a_src = A + (size_t)(bm + a_row) * lda + a_sel * 4;

    int b_k2 = tid >> 5;
    int b_nb = (tid & 31) * 4;
    const float* b_src0 = B + (size_t)(2 * b_k2)     * ldb + bn + b_nb;
    const float* b_src1 = B + (size_t)(2 * b_k2 + 1) * ldb + bn + b_nb;

    float va0[4], va1[4], vb0[4], vb1[4];

#define LOAD_SLAB(k0) do {                                                    \
        if (a_load) {                                                         \
            float4 t0 = *reinterpret_cast<const float4*>(a_src + (k0));       \
            float4 t1 = *reinterpret_cast<const float4*>(a_src + (k0) + 8);   \
            va0[0]=t0.x; va0[1]=t0.y; va0[2]=t0.z; va0[3]=t0.w;               \
            va1[0]=t1.x; va1[1]=t1.y; va1[2]=t1.z; va1[3]=t1.w;               \
        } else {                                                              \
            va0[0]=va0[1]=va0[2]=va0[3]=0.f;                                  \
            va1[0]=va1[1]=va1[2]=va1[3]=0.f;                                  \
        }                                                                     \
        float4 u0 = *reinterpret_cast<const float4*>(b_src0 + (size_t)(k0) * ldb); \
        float4 u1 = *reinterpret_cast<const float4*>(b_src1 + (size_t)(k0) * ldb); \
        vb0[0]=u0.x; vb0[1]=u0.y; vb0[2]=u0.z; vb0[3]=u0.w;                   \
        vb1[0]=u1.x; vb1[1]=u1.y; vb1[2]=u1.z; vb1[3]=u1.w;                   \
    } while (0)

#define STAGE(buf) do {                                                      \
        *reinterpret_cast<uint4*>(&As[buf][a_row * AS_STRIDE + a_sel * 4]) =  \
            make_uint4(pack_h2(va0[0], va0[1]), pack_h2(va1[0], va1[1]),      \
                       pack_h2(va0[2], va0[3]), pack_h2(va1[2], va1[3]));     \
        *reinterpret_cast<uint4*>(&Bs[buf][b_k2 * BS_STRIDE + b_nb]) =        \
            make_uint4(pack_h2(vb0[0], vb1[0]), pack_h2(vb0[1], vb1[1]),      \
                       pack_h2(vb0[2], vb1[2]), pack_h2(vb0[3], vb1[3]));     \
    } while (0)

    LOAD_SLAB(0);
    STAGE(0);
    __syncthreads();

    for (int it = 0; it < NIT; it++) {
        int cur = it & 1;
        if (it + 1 < NIT) LOAD_SLAB((it + 1) * BK);

        unsigned bf[4][2];
#pragma unroll
        for (int nt = 0; nt < 4; nt++) {
            int n = warp_n + nt * 8 + grp;
            bf[nt][0] = Bs[cur][tig * BS_STRIDE + n];
            bf[nt][1] = Bs[cur][(tig + 4) * BS_STRIDE + n];
        }
#pragma unroll
        for (int mt = 0; mt < 4; mt++) {
            int m = warp_m + mt * 16 + grp;
            uint2 plo = *reinterpret_cast<const uint2*>(&As[cur][m * AS_STRIDE + tig * 2]);
            uint2 phi = *reinterpret_cast<const uint2*>(&As[cur][(m + 8) * AS_STRIDE + tig * 2]);
#pragma unroll
            for (int nt = 0; nt < 4; nt++) {
                asm volatile(
                    "mma.sync.aligned.m16n8k16.row.col.f32.f16.f16.f32 "
                    "{%0,%1,%2,%3}, {%4,%5,%6,%7}, {%8,%9}, {%0,%1,%2,%3};\n"
                    : "+f"(c[mt][nt][0]), "+f"(c[mt][nt][1]),
                      "+f"(c[mt][nt][2]), "+f"(c[mt][nt][3])
                    : "r"(plo.x), "r"(phi.x), "r"(plo.y), "r"(phi.y),
                      "r"(bf[nt][0]), "r"(bf[nt][1]));
            }
        }

        if (it + 1 < NIT) STAGE(1 - cur);
        __syncthreads();
    }
#undef LOAD_SLAB
#undef STAGE

    // --- epilogue: bias (+relu); docrep rows not in union are skipped ---
#pragma unroll
    for (int mt = 0; mt < 4; mt++) {
#pragma unroll
        for (int nt = 0; nt < 4; nt++) {
            int m0 = bm + warp_m + mt * 16 + grp;
            int n0 = bn + warp_n + nt * 8 + tig * 2;
            float b0 = bias[n0], b1 = bias[n0 + 1];
            bool st0 = (m0 < M);
            bool st1 = (m0 + 8 < M);
            if (is_docrep) {
                if (st0) st0 = in_union_s(s_un, doc_ids[m0]);
                if (st1) st1 = in_union_s(s_un, doc_ids[m0 + 8]);
            }
            if (st0) {
                float v0 = c[mt][nt][0] + b0;
                float v1 = c[mt][nt][1] + b1;
                if (relu) { v0 = fmaxf(v0, 0.f); v1 = fmaxf(v1, 0.f); }
                *reinterpret_cast<float2*>(C + (size_t)m0 * ldc + n0) = make_float2(v0, v1);
            }
            if (st1) {
                float v2 = c[mt][nt][2] + b0;
                float v3 = c[mt][nt][3] + b1;
                if (relu) { v2 = fmaxf(v2, 0.f); v3 = fmaxf(v3, 0.f); }
                *reinterpret_cast<float2*>(C + (size_t)(m0 + 8) * ldc + n0) = make_float2(v2, v3);
            }
        }
    }
}

// ---------------------------------------------------------------------------
// Warp-per-(q,d) token scoring + fused cls dot. No smem, no block syncs:
// doc ids live in 6 regs/lane (ballots = pure ALU); rep rows read from L2.
// scores[q,d] = sum_{i>=1} qmask[q,i] * max_{j: dids==qids} dot(...) + clsdot
// ---------------------------------------------------------------------------
__global__ __launch_bounds__(256) void tok_warp(
    const void* __restrict__ cand_a, const void* __restrict__ cand_b,
    const int* __restrict__ dids_g,
    float* __restrict__ scores)
{
    bool a_mask = is_mask_arr(cand_a);
    const int*   qids_g  = (const int*)  (a_mask ? cand_b : cand_a);
    const float* qmask_g = (const float*)(a_mask ? cand_a : cand_b);

    int q    = blockIdx.x;
    int d    = blockIdx.y * 8 + (threadIdx.x >> 5);
    int lane = threadIdx.x & 31;

    int   qid = qids_g[q * LQ_ + lane];
    float qm  = qmask_g[q * LQ_ + lane];

    int dv[6];
#pragma unroll
    for (int b = 0; b < 6; b++)
        dv[b] = dids_g[d * LD_ + b * 32 + lane];

    const float* drb = g_doc_reps + (size_t)d * LD_ * DT_;
    const float* qrb = g_qry_reps + (size_t)q * LQ_ * DT_;

    float acc = 0.f;
    for (int i = 1; i < LQ_; i++) {
        int tok = __shfl_sync(0xffffffffu, qid, i);
        const float* qr = qrb + (size_t)i * DT_;
        float best = 0.f;
#pragma unroll
        for (int b = 0; b < 6; b++) {
            unsigned m = __ballot_sync(0xffffffffu, dv[b] == tok);
            while (m) {
                int jj = b * 32 + (__ffs(m) - 1);
                m &= m - 1;
                const float* dr = drb + (size_t)jj * DT_;
                float p = qr[lane]      * dr[lane]
                        + qr[lane + 32] * dr[lane + 32]
                        + qr[lane + 64] * dr[lane + 64]
                        + qr[lane + 96] * dr[lane + 96];
#pragma unroll
                for (int off = 16; off > 0; off >>= 1)
                    p += __shfl_xor_sync(0xffffffffu, p, off);
                best = fmaxf(best, p);
            }
        }
        acc += best * __shfl_sync(0xffffffffu, qm, i);
    }

    // fused cls dot over 768 dims (6 float4 per lane)
    const float* qc = g_qry_cls + (size_t)q * DC_;
    const float* dc = g_doc_cls + (size_t)d * DC_;
    float pc = 0.f;
#pragma unroll
    for (int k = 0; k < 6; k++) {
        float4 av = *reinterpret_cast<const float4*>(qc + k * 128 + lane * 4);
        float4 bv = *reinterpret_cast<const float4*>(dc + k * 128 + lane * 4);
        pc += av.x * bv.x + av.y * bv.y + av.z * bv.z + av.w * bv.w;
    }
#pragma unroll
    for (int off = 16; off > 0; off >>= 1)
        pc += __shfl_xor_sync(0xffffffffu, pc, off);

    if (lane == 0) scores[q * D_ + d] = acc + pc;
}

// ---------------------------------------------------------------------------
// Fused loss + output layout.
// ---------------------------------------------------------------------------
__global__ __launch_bounds__(1024) void loss_layout_kernel(
    const float* __restrict__ scores, const int* __restrict__ gs,
    float* __restrict__ out, int out_size, int mode)
{
    __shared__ float wloss[32];
    __shared__ float s_loss;
    int tid = threadIdx.x;
    int lane = tid & 31;
    int w = tid >> 5;

    const float* row = scores + (size_t)w * D_;
    float m = -1e30f;
    for (int c = lane; c < D_; c += 32) m = fmaxf(m, row[c]);
#pragma unroll
    for (int off = 16; off > 0; off >>= 1)
        m = fmaxf(m, __shfl_xor_sync(0xffffffffu, m, off));
    float s = 0.f;
    for (int c = lane; c < D_; c += 32) s += expf(row[c] - m);
#pragma unroll
    for (int off = 16; off > 0; off >>= 1)
        s += __shfl_xor_sync(0xffffffffu, s, off);

    int group = 8;
    if (gs) {
        int gv = gs[0];
        if (gv >= 1 && gv * 31 < D_) group = gv;
    }
    int label = w * group;
    float logp = row[label] - m - logf(s);
    if (lane == 0) wloss[w] = -logp;
    __syncthreads();
    if (tid == 0) {
        float t = 0.f;
        for (int i = 0; i < 32; i++) t += wloss[i];
        s_loss = t / 32.f;
    }
    __syncthreads();

    float loss = s_loss;
    for (int i = tid; i < out_size; i += 1024) {
        if (mode == 0) {
            if (i == 0) out[0] = loss;
        } else if (mode == 1) {
            out[i] = (i < Q_ * D_) ? scores[i] : 0.f;
        } else {
            if (i == 0) out[0] = loss;
            else out[i] = (i - 1 < Q_ * D_) ? scores[i - 1] : 0.f;
        }
    }
}

// Diagnostic sentinel
__global__ void diag_kernel(float* out, int missing_mask, int n)
{
    int i = blockIdx.x * blockDim.x + threadIdx.x;
    if (i < n) out[i] = (i == 0) ? (-1.0e6f - (float)missing_mask) : 0.f;
}

// ---------------------------------------------------------------------------
extern "C" void kernel_launch(void* const* d_in, const int* in_sizes, int n_in,
                              void* d_out, int out_size)
{
    const float* qry_hidden = nullptr;
    const float* doc_hidden = nullptr;
    const void*  doc_ids    = nullptr;
    const float* tok_w      = nullptr;
    const float* tok_b      = nullptr;
    const float* cls_w      = nullptr;
    const float* cls_b      = nullptr;
    const int*   gsize      = nullptr;
    const void*  cand_a     = nullptr;
    const void*  cand_b     = nullptr;

    long long div = 0;
    for (int i = 0; i < n_in; i++) {
        if (in_sizes[i] == 37748736)  { div = 1; break; }
        if (in_sizes[i] == 150994944) { div = 4; break; }
    }
    if (div == 0) div = 1;

    for (int i = 0; i < n_in; i++) {
        long long sz = (long long)in_sizes[i] / div;
        switch (sz) {
            case 786432:   qry_hidden = (const float*)d_in[i]; break;
            case 37748736: doc_hidden = (const float*)d_in[i]; break;
            case 49152:    doc_ids    = d_in[i];               break;
            case 98304:    tok_w      = (const float*)d_in[i]; break;
            case 128:      tok_b      = (const float*)d_in[i]; break;
            case 589824:   cls_w      = (const float*)d_in[i]; break;
            case 768:      cls_b      = (const float*)d_in[i]; break;
            case 1:        gsize      = (const int*)d_in[i];   break;
            case 1024:
                if (!cand_a) cand_a = d_in[i]; else cand_b = d_in[i];
                break;
            default:
                if (sz == 2 && div == 4) gsize = (const int*)d_in[i];
                break;
        }
    }

    float* out = (float*)d_out;

    int missing = 0;
    if (!qry_hidden) missing |= 1;
    if (!doc_hidden) missing |= 2;
    if (!doc_ids)    missing |= 4;
    if (!tok_w)      missing |= 8;
    if (!tok_b)      missing |= 16;
    if (!cls_w)      missing |= 32;
    if (!cls_b)      missing |= 64;
    if (!cand_a)     missing |= 128;
    if (!cand_b)     missing |= 256;
    if (missing) {
        int n = out_size > 0 ? out_size : 1;
        diag_kernel<<<(n + 255) / 256, 256>>>(out, missing, n);
        return;
    }

    float *doc_reps, *qry_reps, *doc_cls, *qry_cls, *scores;
    cudaGetSymbolAddress((void**)&doc_reps, g_doc_reps);
    cudaGetSymbolAddress((void**)&qry_reps, g_qry_reps);
    cudaGetSymbolAddress((void**)&doc_cls,  g_doc_cls);
    cudaGetSymbolAddress((void**)&qry_cls,  g_qry_cls);
    cudaGetSymbolAddress((void**)&scores,   g_scores);

    // 0) union bitmap of query token ids (positions >= 1)
    prep_union<<<1, 1024>>>(cand_a, cand_b);

    // 1) four projections in one wave; docrep rows outside union skipped
    mega_gemm_tc<<<NB_TOTAL, 256>>>(doc_hidden, qry_hidden, (const int*)doc_ids,
                                    tok_w, tok_b, cls_w, cls_b,
                                    doc_reps, qry_reps, doc_cls, qry_cls);
    // 2) warp-per-(q,d) token scores + cls dots -> g_scores
    {
        dim3 grid(Q_, D_ / 8);
        tok_warp<<<grid, 256>>>(cand_a, cand_b, (const int*)doc_ids, scores);
    }
    // 3) fused loss + output layout
    int mode = (out_size == 1) ? 0 : (out_size == Q_ * D_) ? 1 : 2;
    loss_layout_kernel<<<1, 1024>>>(scores, gsize, out, out_size, mode);
}